// round 1
// baseline (speedup 1.0000x reference)
#include <cuda_runtime.h>

#define BN 131072
#define TT 8
#define VV 65
#define CC 32
#define HH 4
#define DD 8
#define BTV (BN * TT * VV)   // 68157440

__device__ float g_loss;

// shared-memory layout (float offsets)
#define OFF_TOK 0            // 65*32 = 2080
#define OFF_POS 2080         // 8*32  = 256
#define OFF_WQ  2336         // 32*32 = 1024  [c][h*8+d]
#define OFF_WK  3360
#define OFF_WV  4384
#define OFF_WFF 5408         // 32*32
#define OFF_BFF 6432         // 32
#define OFF_WLM 6464         // 32*65 = 2080
#define OFF_BLM 8544         // 65
#define OFF_WS  8612         // 16B aligned (8612*4 % 16 == 0)
#define WS_PER_WARP 1152
#define NWARPS 8
#define SMEM_FLOATS (OFF_WS + NWARPS * WS_PER_WARP)   // 17828 -> 71312 B

__global__ void __launch_bounds__(256, 2) zero_loss_kernel() { g_loss = 0.0f; }

__global__ void finalize_kernel(float* out, int out_size) {
    if (out_size >= BTV + 1) out[BTV] = g_loss * (1.0f / (float)(BN * TT));
    else if (out_size == 1)  out[0]   = g_loss * (1.0f / (float)(BN * TT));
}

__global__ void __launch_bounds__(256, 2) fused_bigram_kernel(
    const int* __restrict__ idx, const int* __restrict__ targets,
    const float* __restrict__ tok_emb, const float* __restrict__ pos_emb,
    const float* __restrict__ wq, const float* __restrict__ wk, const float* __restrict__ wv,
    const float* __restrict__ w_ff, const float* __restrict__ b_ff,
    const float* __restrict__ w_lm, const float* __restrict__ b_lm,
    float* __restrict__ out, int write_logits)
{
    extern __shared__ float sm[];
    const int tid = threadIdx.x;

    // ---- stage all weights into shared ----
    for (int i = tid; i < VV * CC; i += blockDim.x) sm[OFF_TOK + i] = tok_emb[i];
    for (int i = tid; i < TT * CC; i += blockDim.x) sm[OFF_POS + i] = pos_emb[i];
    for (int i = tid; i < HH * CC * DD; i += blockDim.x) {
        int h = i >> 8, c = (i >> 3) & 31, d = i & 7;
        int o = c * 32 + h * 8 + d;          // [c][hd]
        sm[OFF_WQ + o] = wq[i];
        sm[OFF_WK + o] = wk[i];
        sm[OFF_WV + o] = wv[i];
    }
    for (int i = tid; i < CC * CC; i += blockDim.x) sm[OFF_WFF + i] = w_ff[i];
    for (int i = tid; i < CC;      i += blockDim.x) sm[OFF_BFF + i] = b_ff[i];
    for (int i = tid; i < CC * VV; i += blockDim.x) sm[OFF_WLM + i] = w_lm[i];
    for (int i = tid; i < VV;      i += blockDim.x) sm[OFF_BLM + i] = b_lm[i];
    __syncthreads();

    const int lane = tid & 31;
    const int warp = tid >> 5;
    float* ws = sm + OFF_WS + warp * WS_PER_WARP;
    float* xo = ws;            // [c][t] stride 12 floats (384)
    float* qb = ws + 384;      // [h*64 + t*8 + d] (256)
    float* kb = ws + 640;      // (256)
    float* vb = ws + 896;      // (256)
    float* hb = ws + 640;      // reuse kb after attention, [c][t] stride 8
    float* ls = ws;            // logits staging [t*65+v] (520), reuses xo+qb

    const int gw = blockIdx.x * (blockDim.x >> 5) + warp;
    const int nw = gridDim.x * (blockDim.x >> 5);
    const float SCALE = 0.17677669529663687f;  // 32^-0.5 (reference uses n_embd^-0.5)

    float lossAcc = 0.0f;

    for (int b = gw; b < BN; b += nw) {
        // ---- phase 1: x[t][c] = tok_emb[idx] + pos_emb, lane = c ----
        int tok = 0;
        if (lane < TT) tok = idx[b * TT + lane];
        #pragma unroll
        for (int t = 0; t < TT; t++) {
            int tt = __shfl_sync(0xffffffffu, tok, t);
            xo[lane * 12 + t] = sm[OFF_TOK + tt * 32 + lane] + sm[OFF_POS + t * 32 + lane];
        }
        __syncwarp();

        // ---- phase 2: QKV, lane = h*8+d ----
        float q[8], k[8], v[8];
        #pragma unroll
        for (int t = 0; t < 8; t++) { q[t] = 0.f; k[t] = 0.f; v[t] = 0.f; }
        #pragma unroll 8
        for (int c = 0; c < 32; c++) {
            const float4 xa = *(const float4*)(xo + c * 12);
            const float4 xb = *(const float4*)(xo + c * 12 + 4);
            const float wqc = sm[OFF_WQ + c * 32 + lane];
            const float wkc = sm[OFF_WK + c * 32 + lane];
            const float wvc = sm[OFF_WV + c * 32 + lane];
            float xs[8] = {xa.x, xa.y, xa.z, xa.w, xb.x, xb.y, xb.z, xb.w};
            #pragma unroll
            for (int t = 0; t < 8; t++) {
                q[t] = fmaf(xs[t], wqc, q[t]);
                k[t] = fmaf(xs[t], wkc, k[t]);
                v[t] = fmaf(xs[t], wvc, v[t]);
            }
        }
        {
            const int h8 = (lane >> 3) * 64, dd = lane & 7;
            #pragma unroll
            for (int t = 0; t < 8; t++) {
                qb[h8 + t * 8 + dd] = q[t];
                kb[h8 + t * 8 + dd] = k[t];
                vb[h8 + t * 8 + dd] = v[t];
            }
        }
        __syncwarp();

        // ---- phase 3: causal attention, lane -> (h = lane>>3, t = lane&7) ----
        const int hh = (lane >> 3) * 64;
        const int tq = lane & 7;
        float w8[8];
        {
            const float4 qa = *(const float4*)(qb + hh + tq * 8);
            const float4 qc = *(const float4*)(qb + hh + tq * 8 + 4);
            float m = -1e30f;
            #pragma unroll
            for (int s = 0; s < 8; s++) {
                const float4 ka = *(const float4*)(kb + hh + s * 8);
                const float4 kc = *(const float4*)(kb + hh + s * 8 + 4);
                float acc = qa.x * ka.x;
                acc = fmaf(qa.y, ka.y, acc);
                acc = fmaf(qa.z, ka.z, acc);
                acc = fmaf(qa.w, ka.w, acc);
                acc = fmaf(qc.x, kc.x, acc);
                acc = fmaf(qc.y, kc.y, acc);
                acc = fmaf(qc.z, kc.z, acc);
                acc = fmaf(qc.w, kc.w, acc);
                acc *= SCALE;
                acc = (s <= tq) ? acc : -1e30f;
                w8[s] = acc;
                m = fmaxf(m, acc);
            }
            float ssum = 0.f;
            #pragma unroll
            for (int s = 0; s < 8; s++) {
                float e = __expf(w8[s] - m);   // masked entries underflow to 0
                w8[s] = e;
                ssum += e;
            }
            const float inv = __fdividef(1.0f, ssum);
            #pragma unroll
            for (int s = 0; s < 8; s++) w8[s] *= inv;
        }

        // ---- phase 4: o = w @ v ----
        float o8[8];
        #pragma unroll
        for (int d = 0; d < 8; d++) o8[d] = 0.f;
        #pragma unroll
        for (int s = 0; s < 8; s++) {
            const float4 va = *(const float4*)(vb + hh + s * 8);
            const float4 vc = *(const float4*)(vb + hh + s * 8 + 4);
            o8[0] = fmaf(w8[s], va.x, o8[0]);
            o8[1] = fmaf(w8[s], va.y, o8[1]);
            o8[2] = fmaf(w8[s], va.z, o8[2]);
            o8[3] = fmaf(w8[s], va.w, o8[3]);
            o8[4] = fmaf(w8[s], vc.x, o8[4]);
            o8[5] = fmaf(w8[s], vc.y, o8[5]);
            o8[6] = fmaf(w8[s], vc.z, o8[6]);
            o8[7] = fmaf(w8[s], vc.w, o8[7]);
        }
        __syncwarp();   // everyone done reading xo/qb/kb/vb before overwrite
        {
            const int hbase = (lane >> 3) * 8;
            #pragma unroll
            for (int d = 0; d < 8; d++) xo[(hbase + d) * 12 + tq] = o8[d];
        }
        __syncwarp();

        // ---- phase 5: FF + ReLU, lane = j ----
        float hf[8];
        {
            const float bf = sm[OFF_BFF + lane];
            #pragma unroll
            for (int t = 0; t < 8; t++) hf[t] = bf;
        }
        #pragma unroll 8
        for (int c = 0; c < 32; c++) {
            const float4 oa = *(const float4*)(xo + c * 12);
            const float4 ob = *(const float4*)(xo + c * 12 + 4);
            const float wf = sm[OFF_WFF + c * 32 + lane];
            float osv[8] = {oa.x, oa.y, oa.z, oa.w, ob.x, ob.y, ob.z, ob.w};
            #pragma unroll
            for (int t = 0; t < 8; t++) hf[t] = fmaf(osv[t], wf, hf[t]);
        }
        #pragma unroll
        for (int t = 0; t < 8; t++) hf[t] = fmaxf(hf[t], 0.0f);
        __syncwarp();   // kb (=hb) free now
        #pragma unroll
        for (int t = 0; t < 8; t++) hb[lane * 8 + t] = hf[t];
        __syncwarp();

        // ---- phase 6: LM head, chunks v = lane, lane+32; then v=64 ----
        #pragma unroll
        for (int chunk = 0; chunk < 2; chunk++) {
            const int vv = chunk * 32 + lane;
            float lg[8];
            {
                const float bl = sm[OFF_BLM + vv];
                #pragma unroll
                for (int t = 0; t < 8; t++) lg[t] = bl;
            }
            #pragma unroll 8
            for (int c = 0; c < 32; c++) {
                const float4 ha = *(const float4*)(hb + c * 8);
                const float4 hc = *(const float4*)(hb + c * 8 + 4);
                const float wl = sm[OFF_WLM + c * 65 + vv];
                float hv[8] = {ha.x, ha.y, ha.z, ha.w, hc.x, hc.y, hc.z, hc.w};
                #pragma unroll
                for (int t = 0; t < 8; t++) lg[t] = fmaf(hv[t], wl, lg[t]);
            }
            #pragma unroll
            for (int t = 0; t < 8; t++) ls[t * 65 + vv] = lg[t];
        }
        {   // v = 64 column: lanes (t = lane>>2, part = lane&3), each sums 8 c's
            const int t64 = lane >> 2, part = lane & 3;
            float p = 0.f;
            #pragma unroll
            for (int c8 = 0; c8 < 8; c8++) {
                const int c = part * 8 + c8;
                p = fmaf(hb[c * 8 + t64], sm[OFF_WLM + c * 65 + 64], p);
            }
            p += __shfl_xor_sync(0xffffffffu, p, 1);
            p += __shfl_xor_sync(0xffffffffu, p, 2);
            if (part == 0) ls[t64 * 65 + 64] = p + sm[OFF_BLM + 64];
        }
        __syncwarp();

        // ---- write logits: 130 float4 per batch row, fully coalesced ----
        if (write_logits) {
            float4* outp = (float4*)out + (size_t)b * 130;
            for (int i = lane; i < 130; i += 32)
                outp[i] = *(const float4*)(ls + i * 4);
        }

        // ---- loss: lse per (b,t) over 65, lanes (part = lane>>3, t = lane&7) ----
        {
            const int part = lane >> 3, t = lane & 7;
            const int lo = part * 16;
            const int hi = lo + 16 + (part == 3 ? 1 : 0);
            float m2 = -1e30f;
            for (int vi = lo; vi < hi; vi++) m2 = fmaxf(m2, ls[t * 65 + vi]);
            m2 = fmaxf(m2, __shfl_xor_sync(0xffffffffu, m2, 8));
            m2 = fmaxf(m2, __shfl_xor_sync(0xffffffffu, m2, 16));
            float se = 0.f;
            for (int vi = lo; vi < hi; vi++) se += __expf(ls[t * 65 + vi] - m2);
            se += __shfl_xor_sync(0xffffffffu, se, 8);
            se += __shfl_xor_sync(0xffffffffu, se, 16);
            if (part == 0) {
                const int tg = targets[b * TT + t];
                lossAcc += (m2 + __logf(se)) - ls[t * 65 + tg];
            }
        }
        __syncwarp();   // ls (=xo) reused next iteration
    }

    // ---- reduce loss ----
    #pragma unroll
    for (int off = 16; off; off >>= 1)
        lossAcc += __shfl_xor_sync(0xffffffffu, lossAcc, off);
    if (lane == 0 && lossAcc != 0.0f) atomicAdd(&g_loss, lossAcc);
    else if (lane == 0) atomicAdd(&g_loss, 0.0f);
}

extern "C" void kernel_launch(void* const* d_in, const int* in_sizes, int n_in,
                              void* d_out, int out_size) {
    const int*   idx     = (const int*)d_in[0];
    const int*   targets = (const int*)d_in[1];
    const float* tok_emb = (const float*)d_in[2];
    const float* pos_emb = (const float*)d_in[3];
    const float* wq      = (const float*)d_in[4];
    const float* wk      = (const float*)d_in[5];
    const float* wv      = (const float*)d_in[6];
    const float* w_ff    = (const float*)d_in[7];
    const float* b_ff    = (const float*)d_in[8];
    const float* w_lm    = (const float*)d_in[9];
    const float* b_lm    = (const float*)d_in[10];
    float* out = (float*)d_out;

    cudaFuncSetAttribute(fused_bigram_kernel,
                         cudaFuncAttributeMaxDynamicSharedMemorySize,
                         SMEM_FLOATS * sizeof(float));

    const int write_logits = (out_size >= BTV) ? 1 : 0;

    zero_loss_kernel<<<1, 1>>>();
    fused_bigram_kernel<<<304, 256, SMEM_FLOATS * sizeof(float)>>>(
        idx, targets, tok_emb, pos_emb, wq, wk, wv, w_ff, b_ff, w_lm, b_lm,
        out, write_logits);
    finalize_kernel<<<1, 1>>>(out, out_size);
}

// round 2
// speedup vs baseline: 1.0149x; 1.0149x over previous
#include <cuda_runtime.h>

#define BN 131072
#define TT 8
#define VV 65
#define CC 32
#define HH 4
#define DD 8
#define BTV (BN * TT * VV)   // 68157440

__device__ float g_loss;     // zero-initialized at module load; finalize resets after use

// shared-memory layout (float offsets)
#define OFF_TOK 0            // 65*32 = 2080
#define OFF_POS 2080         // 8*32  = 256
#define OFF_WQ  2336         // 32*32 = 1024  [c][h*8+d]
#define OFF_WK  3360
#define OFF_WV  4384
#define OFF_WFF 5408         // 32*32
#define OFF_BFF 6432         // 32
#define OFF_WLM 6464         // 32*65 = 2080
#define OFF_BLM 8544         // 65
#define OFF_WS  8612         // 16B aligned
#define WS_PER_WARP 1152
#define NWARPS 8
#define SMEM_FLOATS (OFF_WS + NWARPS * WS_PER_WARP)   // 17828 floats -> 71312 B

typedef unsigned long long u64;

// ---- packed fp32x2 helpers (FFMA2 — not emitted by ptxas from C++) ----
__device__ __forceinline__ u64 pk2(float lo, float hi) {
    u64 r; asm("mov.b64 %0, {%1, %2};" : "=l"(r) : "f"(lo), "f"(hi)); return r;
}
__device__ __forceinline__ u64 dup2(float v) { return pk2(v, v); }
__device__ __forceinline__ u64 ffma2(u64 a, u64 b, u64 c) {
    u64 d; asm("fma.rn.f32x2 %0, %1, %2, %3;" : "=l"(d) : "l"(a), "l"(b), "l"(c)); return d;
}
__device__ __forceinline__ float2 up2(u64 p) {
    float2 f; asm("mov.b64 {%0, %1}, %2;" : "=f"(f.x), "=f"(f.y) : "l"(p)); return f;
}

__global__ void finalize_kernel(float* out, int out_size) {
    float l = g_loss * (1.0f / (float)(BN * TT));
    if (out_size >= BTV + 1) out[BTV] = l;
    else if (out_size == 1)  out[0]   = l;
    g_loss = 0.0f;   // reset for next graph replay (deterministic)
}

__global__ void __launch_bounds__(256, 2) fused_bigram_kernel(
    const int* __restrict__ idx, const int* __restrict__ targets,
    const float* __restrict__ tok_emb, const float* __restrict__ pos_emb,
    const float* __restrict__ wq, const float* __restrict__ wk, const float* __restrict__ wv,
    const float* __restrict__ w_ff, const float* __restrict__ b_ff,
    const float* __restrict__ w_lm, const float* __restrict__ b_lm,
    float* __restrict__ out, int write_logits)
{
    extern __shared__ float sm[];
    const int tid = threadIdx.x;

    // ---- stage all weights into shared ----
    for (int i = tid; i < VV * CC; i += blockDim.x) sm[OFF_TOK + i] = tok_emb[i];
    for (int i = tid; i < TT * CC; i += blockDim.x) sm[OFF_POS + i] = pos_emb[i];
    for (int i = tid; i < HH * CC * DD; i += blockDim.x) {
        int h = i >> 8, c = (i >> 3) & 31, d = i & 7;
        int o = c * 32 + h * 8 + d;          // [c][hd]
        sm[OFF_WQ + o] = wq[i];
        sm[OFF_WK + o] = wk[i];
        sm[OFF_WV + o] = wv[i];
    }
    for (int i = tid; i < CC * CC; i += blockDim.x) sm[OFF_WFF + i] = w_ff[i];
    for (int i = tid; i < CC;      i += blockDim.x) sm[OFF_BFF + i] = b_ff[i];
    for (int i = tid; i < CC * VV; i += blockDim.x) sm[OFF_WLM + i] = w_lm[i];
    for (int i = tid; i < VV;      i += blockDim.x) sm[OFF_BLM + i] = b_lm[i];
    __syncthreads();

    const int lane = tid & 31;
    const int warp = tid >> 5;
    float* ws = sm + OFF_WS + warp * WS_PER_WARP;
    float* xo = ws;            // [c][t] stride 12 floats (384)
    float* qb = ws + 384;      // [h*64 + t*8 + d] (256)
    float* kb = ws + 640;      // (256)
    float* vb = ws + 896;      // (256)
    float* hb = ws + 640;      // reuse kb after attention, [c][t] stride 8
    float* ls = ws;            // logits staging [t*65+v] (520), reuses xo+qb

    const int gw = blockIdx.x * (blockDim.x >> 5) + warp;
    const int nw = gridDim.x * (blockDim.x >> 5);
    const float SCALE = 0.17677669529663687f;  // 32^-0.5 (reference uses n_embd^-0.5)

    float lossAcc = 0.0f;

    for (int b = gw; b < BN; b += nw) {
        // ---- phase 1: x[t][c] = tok_emb[idx] + pos_emb, lane = c ----
        int tok = 0;
        if (lane < TT) tok = idx[b * TT + lane];
        #pragma unroll
        for (int t = 0; t < TT; t++) {
            int tt = __shfl_sync(0xffffffffu, tok, t);
            xo[lane * 12 + t] = sm[OFF_TOK + tt * 32 + lane] + sm[OFF_POS + t * 32 + lane];
        }
        __syncwarp();

        // ---- phase 2: QKV (packed over t-pairs), lane = h*8+d ----
        u64 q2[4], k2[4], v2[4];
        #pragma unroll
        for (int i = 0; i < 4; i++) { q2[i] = 0ull; k2[i] = 0ull; v2[i] = 0ull; }
        #pragma unroll 8
        for (int c = 0; c < 32; c++) {
            const ulonglong2 x01 = *(const ulonglong2*)(xo + c * 12);      // t0t1, t2t3
            const ulonglong2 x23 = *(const ulonglong2*)(xo + c * 12 + 4);  // t4t5, t6t7
            const u64 xp0 = x01.x, xp1 = x01.y, xp2 = x23.x, xp3 = x23.y;
            const u64 wq2 = dup2(sm[OFF_WQ + c * 32 + lane]);
            const u64 wk2 = dup2(sm[OFF_WK + c * 32 + lane]);
            const u64 wv2 = dup2(sm[OFF_WV + c * 32 + lane]);
            q2[0] = ffma2(xp0, wq2, q2[0]); q2[1] = ffma2(xp1, wq2, q2[1]);
            q2[2] = ffma2(xp2, wq2, q2[2]); q2[3] = ffma2(xp3, wq2, q2[3]);
            k2[0] = ffma2(xp0, wk2, k2[0]); k2[1] = ffma2(xp1, wk2, k2[1]);
            k2[2] = ffma2(xp2, wk2, k2[2]); k2[3] = ffma2(xp3, wk2, k2[3]);
            v2[0] = ffma2(xp0, wv2, v2[0]); v2[1] = ffma2(xp1, wv2, v2[1]);
            v2[2] = ffma2(xp2, wv2, v2[2]); v2[3] = ffma2(xp3, wv2, v2[3]);
        }
        {
            const int h8 = (lane >> 3) * 64, dd = lane & 7;
            #pragma unroll
            for (int i = 0; i < 4; i++) {
                const float2 fq = up2(q2[i]), fk = up2(k2[i]), fv = up2(v2[i]);
                qb[h8 + (2 * i    ) * 8 + dd] = fq.x;
                qb[h8 + (2 * i + 1) * 8 + dd] = fq.y;
                kb[h8 + (2 * i    ) * 8 + dd] = fk.x;
                kb[h8 + (2 * i + 1) * 8 + dd] = fk.y;
                vb[h8 + (2 * i    ) * 8 + dd] = fv.x;
                vb[h8 + (2 * i + 1) * 8 + dd] = fv.y;
            }
        }
        __syncwarp();

        // ---- phase 3: causal attention scores (packed over d-pairs) ----
        const int hh = (lane >> 3) * 64;
        const int tq = lane & 7;
        float w8[8];
        {
            const ulonglong2 qA = *(const ulonglong2*)(qb + hh + tq * 8);
            const ulonglong2 qB = *(const ulonglong2*)(qb + hh + tq * 8 + 4);
            float m = -1e30f;
            #pragma unroll
            for (int s = 0; s < 8; s++) {
                const ulonglong2 kA = *(const ulonglong2*)(kb + hh + s * 8);
                const ulonglong2 kB = *(const ulonglong2*)(kb + hh + s * 8 + 4);
                u64 p = ffma2(qA.x, kA.x, 0ull);
                p = ffma2(qA.y, kA.y, p);
                p = ffma2(qB.x, kB.x, p);
                p = ffma2(qB.y, kB.y, p);
                const float2 f = up2(p);
                float acc = (f.x + f.y) * SCALE;
                acc = (s <= tq) ? acc : -1e30f;
                w8[s] = acc;
                m = fmaxf(m, acc);
            }
            float ssum = 0.f;
            #pragma unroll
            for (int s = 0; s < 8; s++) {
                float e = __expf(w8[s] - m);   // masked entries underflow to 0
                w8[s] = e;
                ssum += e;
            }
            const float inv = __fdividef(1.0f, ssum);
            #pragma unroll
            for (int s = 0; s < 8; s++) w8[s] *= inv;
        }

        // ---- phase 4: o = w @ v (packed over d-pairs) ----
        u64 o2[4];
        #pragma unroll
        for (int i = 0; i < 4; i++) o2[i] = 0ull;
        #pragma unroll
        for (int s = 0; s < 8; s++) {
            const u64 ws2 = dup2(w8[s]);
            const ulonglong2 vA = *(const ulonglong2*)(vb + hh + s * 8);
            const ulonglong2 vB = *(const ulonglong2*)(vb + hh + s * 8 + 4);
            o2[0] = ffma2(ws2, vA.x, o2[0]);
            o2[1] = ffma2(ws2, vA.y, o2[1]);
            o2[2] = ffma2(ws2, vB.x, o2[2]);
            o2[3] = ffma2(ws2, vB.y, o2[3]);
        }
        __syncwarp();   // everyone done reading xo/qb/kb/vb before overwrite
        {
            const int hbase = (lane >> 3) * 8;
            #pragma unroll
            for (int i = 0; i < 4; i++) {
                const float2 f = up2(o2[i]);
                xo[(hbase + 2 * i    ) * 12 + tq] = f.x;
                xo[(hbase + 2 * i + 1) * 12 + tq] = f.y;
            }
        }
        __syncwarp();

        // ---- phase 5: FF + ReLU (packed over t-pairs), lane = j ----
        u64 hf2[4];
        {
            const u64 bf2 = dup2(sm[OFF_BFF + lane]);
            #pragma unroll
            for (int i = 0; i < 4; i++) hf2[i] = bf2;
        }
        #pragma unroll 8
        for (int c = 0; c < 32; c++) {
            const ulonglong2 o01 = *(const ulonglong2*)(xo + c * 12);
            const ulonglong2 o23 = *(const ulonglong2*)(xo + c * 12 + 4);
            const u64 wf2 = dup2(sm[OFF_WFF + c * 32 + lane]);
            hf2[0] = ffma2(o01.x, wf2, hf2[0]);
            hf2[1] = ffma2(o01.y, wf2, hf2[1]);
            hf2[2] = ffma2(o23.x, wf2, hf2[2]);
            hf2[3] = ffma2(o23.y, wf2, hf2[3]);
        }
        __syncwarp();   // kb (=hb) free now
        #pragma unroll
        for (int i = 0; i < 4; i++) {
            const float2 f = up2(hf2[i]);
            hb[lane * 8 + 2 * i    ] = fmaxf(f.x, 0.0f);
            hb[lane * 8 + 2 * i + 1] = fmaxf(f.y, 0.0f);
        }
        __syncwarp();

        // ---- phase 6: LM head (packed over t-pairs), chunks v = lane, lane+32; then v=64 ----
        #pragma unroll
        for (int chunk = 0; chunk < 2; chunk++) {
            const int vv = chunk * 32 + lane;
            u64 lg2[4];
            {
                const u64 bl2 = dup2(sm[OFF_BLM + vv]);
                #pragma unroll
                for (int i = 0; i < 4; i++) lg2[i] = bl2;
            }
            #pragma unroll 8
            for (int c = 0; c < 32; c++) {
                const ulonglong2 h01 = *(const ulonglong2*)(hb + c * 8);
                const ulonglong2 h23 = *(const ulonglong2*)(hb + c * 8 + 4);
                const u64 wl2 = dup2(sm[OFF_WLM + c * 65 + vv]);
                lg2[0] = ffma2(h01.x, wl2, lg2[0]);
                lg2[1] = ffma2(h01.y, wl2, lg2[1]);
                lg2[2] = ffma2(h23.x, wl2, lg2[2]);
                lg2[3] = ffma2(h23.y, wl2, lg2[3]);
            }
            #pragma unroll
            for (int i = 0; i < 4; i++) {
                const float2 f = up2(lg2[i]);
                ls[(2 * i    ) * 65 + vv] = f.x;
                ls[(2 * i + 1) * 65 + vv] = f.y;
            }
        }
        {   // v = 64 column: lanes (t = lane>>2, part = lane&3), each sums 8 c's
            const int t64 = lane >> 2, part = lane & 3;
            float p = 0.f;
            #pragma unroll
            for (int c8 = 0; c8 < 8; c8++) {
                const int c = part * 8 + c8;
                p = fmaf(hb[c * 8 + t64], sm[OFF_WLM + c * 65 + 64], p);
            }
            p += __shfl_xor_sync(0xffffffffu, p, 1);
            p += __shfl_xor_sync(0xffffffffu, p, 2);
            if (part == 0) ls[t64 * 65 + 64] = p + sm[OFF_BLM + 64];
        }
        __syncwarp();

        // ---- write logits: 130 float4 per batch row, fully coalesced ----
        if (write_logits) {
            float4* outp = (float4*)out + (size_t)b * 130;
            for (int i = lane; i < 130; i += 32)
                outp[i] = *(const float4*)(ls + i * 4);
        }

        // ---- loss: lse per (b,t) over 65, lanes (part = lane>>3, t = lane&7) ----
        {
            const int part = lane >> 3, t = lane & 7;
            const int lo = part * 16;
            const int hi = lo + 16 + (part == 3 ? 1 : 0);
            float m2 = -1e30f;
            for (int vi = lo; vi < hi; vi++) m2 = fmaxf(m2, ls[t * 65 + vi]);
            m2 = fmaxf(m2, __shfl_xor_sync(0xffffffffu, m2, 8));
            m2 = fmaxf(m2, __shfl_xor_sync(0xffffffffu, m2, 16));
            float se = 0.f;
            for (int vi = lo; vi < hi; vi++) se += __expf(ls[t * 65 + vi] - m2);
            se += __shfl_xor_sync(0xffffffffu, se, 8);
            se += __shfl_xor_sync(0xffffffffu, se, 16);
            if (part == 0) {
                const int tg = targets[b * TT + t];
                lossAcc += (m2 + __logf(se)) - ls[t * 65 + tg];
            }
        }
        __syncwarp();   // ls (=xo) reused next iteration
    }

    // ---- reduce loss ----
    #pragma unroll
    for (int off = 16; off; off >>= 1)
        lossAcc += __shfl_xor_sync(0xffffffffu, lossAcc, off);
    if (lane == 0) atomicAdd(&g_loss, lossAcc);
}

extern "C" void kernel_launch(void* const* d_in, const int* in_sizes, int n_in,
                              void* d_out, int out_size) {
    const int*   idx     = (const int*)d_in[0];
    const int*   targets = (const int*)d_in[1];
    const float* tok_emb = (const float*)d_in[2];
    const float* pos_emb = (const float*)d_in[3];
    const float* wq      = (const float*)d_in[4];
    const float* wk      = (const float*)d_in[5];
    const float* wv      = (const float*)d_in[6];
    const float* w_ff    = (const float*)d_in[7];
    const float* b_ff    = (const float*)d_in[8];
    const float* w_lm    = (const float*)d_in[9];
    const float* b_lm    = (const float*)d_in[10];
    float* out = (float*)d_out;

    cudaFuncSetAttribute(fused_bigram_kernel,
                         cudaFuncAttributeMaxDynamicSharedMemorySize,
                         SMEM_FLOATS * sizeof(float));

    const int write_logits = (out_size >= BTV) ? 1 : 0;

    fused_bigram_kernel<<<304, 256, SMEM_FLOATS * sizeof(float)>>>(
        idx, targets, tok_emb, pos_emb, wq, wk, wv, w_ff, b_ff, w_lm, b_lm,
        out, write_logits);
    finalize_kernel<<<1, 1>>>(out, out_size);
}